// round 5
// baseline (speedup 1.0000x reference)
#include <cuda_runtime.h>
#include <cstdint>

#define TSTEPS 60
#define LB 48
#define HZ 12
#define TILE 64
#define NB 128
#define NT 256
#define KT0 17
#define KT1 32
#define SMEMF 52096
#define SMEMB (SMEMF*4)

__device__ float4 g_B0[KT0*64*32];
__device__ float4 g_B1[KT1*64*32];
__device__ float  g_bs0[512], g_bs1[512];

__device__ __forceinline__ float tf32r(float x){
    uint32_t u; asm("cvt.rna.tf32.f32 %0, %1;" : "=r"(u) : "f"(x));
    return __uint_as_float(u);
}

__global__ void pack0(const float* __restrict__ Wih, const float* __restrict__ Whh){
    int idx = blockIdx.x*256 + threadIdx.x;
    if (idx >= KT0*64*32) return;
    int lane = idx&31, nt = (idx>>5)&63, kt = idx>>11;
    int np = nt*8 + (lane>>2);
    int on = (np&3)*128 + (np>>2);          // gate-interleaved packing P=4j+gate
    int k0 = kt*8 + (lane&3), k1 = k0+4;
    float v0 = (k0<8) ? Wih[on*8+k0] : Whh[on*128 + (k0-8)];
    float v1 = (k1<8) ? Wih[on*8+k1] : Whh[on*128 + (k1-8)];
    float h0 = tf32r(v0), h1 = tf32r(v1);
    g_B0[idx] = make_float4(h0, h1, tf32r(v0-h0), tf32r(v1-h1));
}

__global__ void pack1(const float* __restrict__ Wih, const float* __restrict__ Whh){
    int idx = blockIdx.x*256 + threadIdx.x;
    if (idx >= KT1*64*32) return;
    int lane = idx&31, nt = (idx>>5)&63, kt = idx>>11;
    int np = nt*8 + (lane>>2);
    int on = (np&3)*128 + (np>>2);
    int k0 = kt*8 + (lane&3), k1 = k0+4;
    float v0 = (k0<128) ? Wih[on*128+k0] : Whh[on*128 + (k0-128)];
    float v1 = (k1<128) ? Wih[on*128+k1] : Whh[on*128 + (k1-128)];
    float h0 = tf32r(v0), h1 = tf32r(v1);
    g_B1[idx] = make_float4(h0, h1, tf32r(v0-h0), tf32r(v1-h1));
}

__global__ void packb(const float* a,const float* b,const float* c,const float* d){
    int P = threadIdx.x;
    int on = (P&3)*128 + (P>>2);
    g_bs0[P] = a[on]+b[on];
    g_bs1[P] = c[on]+d[on];
}

__device__ __forceinline__ void mma8(float (&c)[4], float4 a, float bx, float by){
    asm volatile("mma.sync.aligned.m16n8k8.row.col.f32.tf32.tf32.f32 "
        "{%0,%1,%2,%3},{%4,%5,%6,%7},{%8,%9},{%0,%1,%2,%3};"
        : "+f"(c[0]),"+f"(c[1]),"+f"(c[2]),"+f"(c[3])
        : "r"(__float_as_uint(a.x)),"r"(__float_as_uint(a.y)),
          "r"(__float_as_uint(a.z)),"r"(__float_as_uint(a.w)),
          "r"(__float_as_uint(bx)),"r"(__float_as_uint(by)));
}

// one K-tile (k8): A frags from smem (hi+lo), B float4 = (bhi0,bhi1,blo0,blo1)
__device__ __forceinline__ void gemm_kt(float (&acc)[4][8][4],
        const float4* __restrict__ AH, const float4* __restrict__ AL,
        int slab0, int slabStride, const float4* __restrict__ Bkt, int lane){
    float4 ah[4], al[4];
#pragma unroll
    for(int mt=0;mt<4;mt++){ int s=(slab0+mt*slabStride)*32+lane; ah[mt]=AH[s]; al[mt]=AL[s]; }
#pragma unroll
    for(int nt=0;nt<8;nt++){
        float4 b = Bkt[nt*32+lane];
#pragma unroll
        for(int mt=0;mt<4;mt++){
            mma8(acc[mt][nt], ah[mt], b.x, b.y);
            mma8(acc[mt][nt], ah[mt], b.z, b.w);
            mma8(acc[mt][nt], al[mt], b.x, b.y);
        }
    }
}

__device__ __forceinline__ float sigf(float x){ return __fdividef(1.f, 1.f+__expf(-x)); }
__device__ __forceinline__ float tanhfast(float x){ return __fdividef(2.f, 1.f+__expf(-2.f*x)) - 1.f; }

__device__ __forceinline__ void epilogue(float (&acc)[4][8][4], int w,int lane,int c4,int gp,int odd,
        const float* __restrict__ BS, float* __restrict__ CS,
        float4* __restrict__ FH, float4* __restrict__ FL, int kbase,
        const float* __restrict__ WF, float* __restrict__ PPT, bool doFC){
    float fc[4] = {0.f,0.f,0.f,0.f};
#pragma unroll
    for(int nt=0;nt<8;nt++){
        int P = w*64 + nt*8 + 2*c4;
        float b0 = BS[P], b1 = BS[P+1];
        int j = w*16 + nt*2 + (c4>>1);
        int k = kbase + j;
        int l2 = (gp<<2) | (k&3);
        int q  = (((k>>2)&1)<<1) | odd;
        int slab = k>>3;
        float wf = doFC ? WF[j] : 0.f;
#pragma unroll
        for(int mt=0;mt<4;mt++){
            float e0 = acc[mt][nt][0]+b0, e1 = acc[mt][nt][1]+b1;
            float e2 = acc[mt][nt][2]+b0, e3 = acc[mt][nt][3]+b1;
            float s0 = odd ? e0 : e2, s1 = odd ? e1 : e3;
            float r0 = __shfl_xor_sync(0xffffffffu, s0, 1);
            float r1 = __shfl_xor_sync(0xffffffffu, s1, 1);
            float gi = odd ? r0 : e0, gf = odd ? r1 : e1;
            float gg = odd ? e2 : r0, go = odd ? e3 : r1;
            int row = mt*16 + gp + 8*odd;
            float cO = CS[row*133 + j];
            float i_ = sigf(gi), f_ = sigf(gf), o_ = sigf(go);
            float g_ = tanhfast(gg);
            float cN = f_*cO + i_*g_;
            float hN = o_*tanhfast(cN);
            CS[row*133 + j] = cN;
            float hi = tf32r(hN), lo = tf32r(hN - hi);
            ((float*)(FH + (mt*32+slab)*32 + l2))[q] = hi;
            ((float*)(FL + (mt*32+slab)*32 + l2))[q] = lo;
            fc[mt] += wf*hN;
        }
    }
    if(doFC){
#pragma unroll
        for(int mt=0;mt<4;mt++){
            float s = fc[mt] + __shfl_xor_sync(0xffffffffu, fc[mt], 2);
            if((lane&2)==0) atomicAdd(&PPT[mt*16 + gp + 8*odd], s);
        }
    }
}

__global__ void __launch_bounds__(NT,1) lstm_main(const float* __restrict__ inputs,
        const float* __restrict__ Wfc, const float* __restrict__ bfc,
        float* __restrict__ out){
    extern __shared__ float sm[];
    float4* F1H = (float4*)sm;             // 4*32 slabs * 32 float4 = 16384 f
    float4* F1L = (float4*)(sm+16384);
    float4* F0H = (float4*)(sm+32768);     // x frags: 4 slabs
    float4* F0L = (float4*)(sm+33280);
    float* CS0 = sm+33792;                 // 64*133
    float* CS1 = sm+42304;
    float* BS0 = sm+50816;
    float* BS1 = sm+51328;
    float* WFs = sm+51840;
    float* PRD = sm+51968;
    float* PPT = sm+52032;

    int tid = threadIdx.x, w = tid>>5, lane = tid&31;
    int c4 = lane&3, gp = lane>>2, odd = c4&1;
    int rb = blockIdx.x*TILE;

    for(int i=tid;i<SMEMF;i+=NT) sm[i]=0.f;
    __syncthreads();
    for(int i=tid;i<512;i+=NT){ BS0[i]=g_bs0[i]; BS1[i]=g_bs1[i]; }
    for(int i=tid;i<128;i+=NT) WFs[i]=Wfc[i];
    __syncthreads();
    float bfcv = bfc[0];

    for(int t=0;t<TSTEPS;t++){
        // scatter x_t into F0 frags (BG feedback for decode steps)
        for(int e=tid;e<512;e+=NT){
            int row=e>>3, d=e&7;
            float v = inputs[(size_t)(rb+row)*(TSTEPS*8) + t*8 + d];
            if(d==0 && t>LB) v = PRD[row];
            float hi=tf32r(v), lo=tf32r(v-hi);
            int mt=row>>4, rr=row&15;
            int l2=((rr&7)<<2)|(d&3), q=(((d>>2)&1)<<1)|(rr>>3);
            ((float*)(F0H + mt*32 + l2))[q]=hi;
            ((float*)(F0L + mt*32 + l2))[q]=lo;
        }
        __syncthreads();

        float acc[4][8][4];
        // -------- layer 0: A=[x | h0_old], K=136 --------
#pragma unroll
        for(int mt=0;mt<4;mt++)
#pragma unroll
            for(int nt=0;nt<8;nt++)
#pragma unroll
                for(int i=0;i<4;i++) acc[mt][nt][i]=0.f;
        gemm_kt(acc, F0H, F0L, 0, 1, g_B0 + (size_t)w*8*32, lane);
#pragma unroll 4
        for(int kt=1;kt<KT0;kt++)
            gemm_kt(acc, F1H, F1L, kt-1, 32, g_B0 + ((size_t)kt*64 + w*8)*32, lane);
        __syncthreads();   // all reads of F1 h0-old done
        epilogue(acc, w,lane,c4,gp,odd, BS0, CS0, F1H, F1L, 0, WFs, PPT, false);
        __syncthreads();

        // -------- layer 1: A=[h0_new | h1_old], K=256 --------
#pragma unroll
        for(int mt=0;mt<4;mt++)
#pragma unroll
            for(int nt=0;nt<8;nt++)
#pragma unroll
                for(int i=0;i<4;i++) acc[mt][nt][i]=0.f;
#pragma unroll 4
        for(int kt=0;kt<KT1;kt++)
            gemm_kt(acc, F1H, F1L, kt, 32, g_B1 + ((size_t)kt*64 + w*8)*32, lane);
        __syncthreads();   // all reads of F1 h1-old done
        bool dec = (t>=LB);
        epilogue(acc, w,lane,c4,gp,odd, BS1, CS1, F1H, F1L, 128, WFs, PPT, dec);
        __syncthreads();

        if(dec){
            if(tid<64){
                float p = PPT[tid] + bfcv;
                PRD[tid] = p; PPT[tid] = 0.f;
                out[(size_t)(rb+tid)*HZ + (t-LB)] = p;
            }
            __syncthreads();
        }
    }
}

extern "C" void kernel_launch(void* const* d_in, const int* in_sizes, int n_in,
                              void* d_out, int out_size) {
    const float* inputs = (const float*)d_in[0];
    const float* Wih0 = (const float*)d_in[1];
    const float* Whh0 = (const float*)d_in[2];
    const float* bih0 = (const float*)d_in[3];
    const float* bhh0 = (const float*)d_in[4];
    const float* Wih1 = (const float*)d_in[5];
    const float* Whh1 = (const float*)d_in[6];
    const float* bih1 = (const float*)d_in[7];
    const float* bhh1 = (const float*)d_in[8];
    const float* Wfc  = (const float*)d_in[9];
    const float* bfc  = (const float*)d_in[10];
    float* out = (float*)d_out;

    cudaFuncSetAttribute(lstm_main, cudaFuncAttributeMaxDynamicSharedMemorySize, SMEMB);

    pack0<<<(KT0*64*32+255)/256, 256>>>(Wih0, Whh0);
    pack1<<<(KT1*64*32+255)/256, 256>>>(Wih1, Whh1);
    packb<<<1, 512>>>(bih0, bhh0, bih1, bhh1);
    lstm_main<<<NB, NT, SMEMB>>>(inputs, Wfc, bfc, out);
}

// round 8
// speedup vs baseline: 1.6276x; 1.6276x over previous
#include <cuda_runtime.h>
#include <cuda_bf16.h>
#include <cstdint>

#define TSTEPS 60
#define LB 48
#define HZ 12
#define TILE 64
#define NB 128
#define NT 256
#define KT0B 9          // k16 tiles, layer0 (K=136 padded to 144)
#define KT1B 16         // k16 tiles, layer1 (K=256)
#define SMEMF 43904
#define SMEMB (SMEMF*4)

__device__ uint4 g_B0[KT0B*64*32];
__device__ uint4 g_B1[KT1B*64*32];
__device__ float g_bs0[512], g_bs1[512];

__device__ __forceinline__ uint32_t pk2(float a, float b){
    __nv_bfloat162 t = __floats2bfloat162_rn(a, b);   // x=a (low half, even k)
    return *reinterpret_cast<uint32_t*>(&t);
}

// split v into bf16 hi + fp32 lo residual
__device__ __forceinline__ void bsplit(float v, float& hi, float& lo){
    __nv_bfloat16 h = __float2bfloat16_rn(v);
    hi = __bfloat162float(h);
    lo = v - hi;
}

__global__ void pack0(const float* __restrict__ Wih, const float* __restrict__ Whh){
    int idx = blockIdx.x*256 + threadIdx.x;
    if (idx >= KT0B*64*32) return;
    int lane = idx&31, nt = (idx>>5)&63, kt = idx>>11;
    int np = nt*8 + (lane>>2);
    int on = (np&3)*128 + (np>>2);           // gate-interleaved col P=4j+gate
    int kb = kt*16 + (lane&3)*2;
    float v[4], h[4], l[4];
    int ks[4] = {kb, kb+1, kb+8, kb+9};
#pragma unroll
    for(int i=0;i<4;i++){
        int k = ks[i];
        v[i] = (k<8) ? Wih[on*8+k] : (k<136 ? Whh[on*128 + (k-8)] : 0.f);
        bsplit(v[i], h[i], l[i]);
    }
    g_B0[idx] = make_uint4(pk2(h[0],h[1]), pk2(h[2],h[3]), pk2(l[0],l[1]), pk2(l[2],l[3]));
}

__global__ void pack1(const float* __restrict__ Wih, const float* __restrict__ Whh){
    int idx = blockIdx.x*256 + threadIdx.x;
    if (idx >= KT1B*64*32) return;
    int lane = idx&31, nt = (idx>>5)&63, kt = idx>>11;
    int np = nt*8 + (lane>>2);
    int on = (np&3)*128 + (np>>2);
    int kb = kt*16 + (lane&3)*2;
    float v[4], h[4], l[4];
    int ks[4] = {kb, kb+1, kb+8, kb+9};
#pragma unroll
    for(int i=0;i<4;i++){
        int k = ks[i];
        v[i] = (k<128) ? Wih[on*128+k] : Whh[on*128 + (k-128)];
        bsplit(v[i], h[i], l[i]);
    }
    g_B1[idx] = make_uint4(pk2(h[0],h[1]), pk2(h[2],h[3]), pk2(l[0],l[1]), pk2(l[2],l[3]));
}

__global__ void packb(const float* a,const float* b,const float* c,const float* d){
    int P = threadIdx.x;
    int on = (P&3)*128 + (P>>2);
    g_bs0[P] = a[on]+b[on];
    g_bs1[P] = c[on]+d[on];
}

__device__ __forceinline__ void mma16(float (&c)[4], uint4 a, uint32_t b0, uint32_t b1){
    asm volatile("mma.sync.aligned.m16n8k16.row.col.f32.bf16.bf16.f32 "
        "{%0,%1,%2,%3},{%4,%5,%6,%7},{%8,%9},{%0,%1,%2,%3};"
        : "+f"(c[0]),"+f"(c[1]),"+f"(c[2]),"+f"(c[3])
        : "r"(a.x),"r"(a.y),"r"(a.z),"r"(a.w),"r"(b0),"r"(b1));
}

// one k16 tile: ahi·bhi + ahi·blo + alo·bhi
__device__ __forceinline__ void gemm_kt(float (&acc)[4][8][4],
        const uint4* __restrict__ AH, const uint4* __restrict__ AL,
        int kt, int KTB, const uint4* __restrict__ Bkt, int lane){
    uint4 ah[4], al[4];
#pragma unroll
    for(int mt=0;mt<4;mt++){
        int s = (mt*KTB + kt)*32 + lane;
        ah[mt] = AH[s]; al[mt] = AL[s];
    }
#pragma unroll
    for(int nt=0;nt<8;nt++){
        uint4 b = Bkt[nt*32+lane];
#pragma unroll
        for(int mt=0;mt<4;mt++){
            mma16(acc[mt][nt], ah[mt], b.x, b.y);
            mma16(acc[mt][nt], ah[mt], b.z, b.w);
            mma16(acc[mt][nt], al[mt], b.x, b.y);
        }
    }
}

__device__ __forceinline__ float sigf(float x){ return __fdividef(1.f, 1.f+__expf(-x)); }
__device__ __forceinline__ float tanhfast(float x){ return __fdividef(2.f, 1.f+__expf(-2.f*x)) - 1.f; }

// store one h element (bf16 hi/lo) into an mma-A-fragment smem buffer
__device__ __forceinline__ void stfrag(uint32_t* FH, uint32_t* FL, int KTB,
        int mt, int gp, int odd, int k, __nv_bfloat16 hb, __nv_bfloat16 lb){
    int kk = k & 15, kt = k >> 4;
    int reg = odd + ((kk>>3)<<1);
    int lane_a = (gp<<2) + ((kk&7)>>1);
    int u = (((mt*KTB + kt)*32 + lane_a)<<2) + reg;
    ((__nv_bfloat16*)FH)[u*2 + (kk&1)] = hb;
    ((__nv_bfloat16*)FL)[u*2 + (kk&1)] = lb;
}

__device__ __forceinline__ void epilogue(float (&acc)[4][8][4], int w,int lane,int c4,int gp,int odd,
        const float* __restrict__ BS, float* __restrict__ CS,
        uint32_t* F1h, uint32_t* F1l, int kb1, int KTB1,
        uint32_t* F2h, uint32_t* F2l, int kb2, int KTB2, bool dual,
        const float* __restrict__ WF, float* __restrict__ PPT, bool doFC){
    float fc[4] = {0.f,0.f,0.f,0.f};
#pragma unroll
    for(int nt=0;nt<8;nt++){
        int P = w*64 + nt*8 + 2*c4;
        float b0 = BS[P], b1 = BS[P+1];
        int j = w*16 + nt*2 + (c4>>1);
        float wf = doFC ? WF[j] : 0.f;
#pragma unroll
        for(int mt=0;mt<4;mt++){
            float e0 = acc[mt][nt][0]+b0, e1 = acc[mt][nt][1]+b1;
            float e2 = acc[mt][nt][2]+b0, e3 = acc[mt][nt][3]+b1;
            float s0 = odd ? e0 : e2, s1 = odd ? e1 : e3;
            float r0 = __shfl_xor_sync(0xffffffffu, s0, 1);
            float r1 = __shfl_xor_sync(0xffffffffu, s1, 1);
            float gi = odd ? r0 : e0, gf = odd ? r1 : e1;
            float gg = odd ? e2 : r0, go = odd ? e3 : r1;
            int row = mt*16 + gp + 8*odd;
            float cO = CS[row*133 + j];
            float i_ = sigf(gi), f_ = sigf(gf), o_ = sigf(go);
            float g_ = tanhfast(gg);
            float cN = f_*cO + i_*g_;
            float hN = o_*tanhfast(cN);
            CS[row*133 + j] = cN;
            __nv_bfloat16 hb = __float2bfloat16_rn(hN);
            __nv_bfloat16 lb = __float2bfloat16_rn(hN - __bfloat162float(hb));
            stfrag(F1h, F1l, KTB1, mt, gp, odd, kb1 + j, hb, lb);
            if(dual) stfrag(F2h, F2l, KTB2, mt, gp, odd, kb2 + j, hb, lb);
            fc[mt] += wf*hN;
        }
    }
    if(doFC){
#pragma unroll
        for(int mt=0;mt<4;mt++){
            float s = fc[mt] + __shfl_xor_sync(0xffffffffu, fc[mt], 2);
            if((lane&2)==0) atomicAdd(&PPT[mt*16 + gp + 8*odd], s);
        }
    }
}

__global__ void __launch_bounds__(NT,1) lstm_main(const float* __restrict__ inputs,
        const float* __restrict__ Wfc, const float* __restrict__ bfc,
        float* __restrict__ out){
    extern __shared__ float sm[];
    uint32_t* F1H = (uint32_t*)sm;            // 4*16*32*4 u32 = 8192
    uint32_t* F1L = (uint32_t*)(sm+8192);
    uint32_t* F0H = (uint32_t*)(sm+16384);    // 4*9*32*4 = 4608
    uint32_t* F0L = (uint32_t*)(sm+20992);
    float* CS0 = sm+25600;                    // 64*133 = 8512
    float* CS1 = sm+34112;
    float* BS0 = sm+42624;
    float* BS1 = sm+43136;
    float* WFs = sm+43648;
    float* PRD = sm+43776;
    float* PPT = sm+43840;

    int tid = threadIdx.x, w = tid>>5, lane = tid&31;
    int c4 = lane&3, gp = lane>>2, odd = c4&1;
    int rb = blockIdx.x*TILE;

    for(int i=tid;i<SMEMF;i+=NT) sm[i]=0.f;
    __syncthreads();
    for(int i=tid;i<512;i+=NT){ BS0[i]=g_bs0[i]; BS1[i]=g_bs1[i]; }
    for(int i=tid;i<128;i+=NT) WFs[i]=Wfc[i];
    __syncthreads();
    float bfcv = bfc[0];

    for(int t=0;t<TSTEPS;t++){
        // scatter x_t into F0 frags, k = d (BG feedback for decode steps)
        for(int e=tid;e<512;e+=NT){
            int row=e>>3, d=e&7;
            float v = inputs[(size_t)(rb+row)*(TSTEPS*8) + t*8 + d];
            if(d==0 && t>LB) v = PRD[row];
            __nv_bfloat16 hb = __float2bfloat16_rn(v);
            __nv_bfloat16 lb = __float2bfloat16_rn(v - __bfloat162float(hb));
            int mt=row>>4, rr=row&15;
            int reg = (rr>>3);                          // k<8 -> high-k reg bit 0
            int lane_a = ((rr&7)<<2) + (d>>1);
            int u = ((mt*KT0B*32 + lane_a)<<2) + reg;
            ((__nv_bfloat16*)F0H)[u*2 + (d&1)] = hb;
            ((__nv_bfloat16*)F0L)[u*2 + (d&1)] = lb;
        }
        __syncthreads();

        float acc[4][8][4];
        // -------- layer 0: A=[x | h0_old], K=136 (9 k16 tiles) --------
#pragma unroll
        for(int mt=0;mt<4;mt++)
#pragma unroll
            for(int nt=0;nt<8;nt++)
#pragma unroll
                for(int i=0;i<4;i++) acc[mt][nt][i]=0.f;
#pragma unroll 3
        for(int kt=0;kt<KT0B;kt++)
            gemm_kt(acc, (const uint4*)F0H, (const uint4*)F0L, kt, KT0B,
                    g_B0 + ((size_t)kt*64 + w*8)*32, lane);
        __syncthreads();   // all reads of F0 h0_old done
        // h0_new -> F0 (k=8+j, next step) and F1 (k=j, layer1 now)
        epilogue(acc, w,lane,c4,gp,odd, BS0, CS0,
                 F0H, F0L, 8, KT0B, F1H, F1L, 0, KT1B, true,
                 WFs, PPT, false);
        __syncthreads();

        // -------- layer 1: A=[h0_new | h1_old], K=256 (16 k16 tiles) --------
#pragma unroll
        for(int mt=0;mt<4;mt++)
#pragma unroll
            for(int nt=0;nt<8;nt++)
#pragma unroll
                for(int i=0;i<4;i++) acc[mt][nt][i]=0.f;
#pragma unroll 3
        for(int kt=0;kt<KT1B;kt++)
            gemm_kt(acc, (const uint4*)F1H, (const uint4*)F1L, kt, KT1B,
                    g_B1 + ((size_t)kt*64 + w*8)*32, lane);
        __syncthreads();   // all reads of F1 h1_old done
        bool dec = (t>=LB);
        epilogue(acc, w,lane,c4,gp,odd, BS1, CS1,
                 F1H, F1L, 128, KT1B, (uint32_t*)0, (uint32_t*)0, 0, 0, false,
                 WFs, PPT, dec);
        __syncthreads();

        if(dec){
            if(tid<64){
                float p = PPT[tid] + bfcv;
                PRD[tid] = p; PPT[tid] = 0.f;
                out[(size_t)(rb+tid)*HZ + (t-LB)] = p;
            }
            __syncthreads();
        }
    }
}

extern "C" void kernel_launch(void* const* d_in, const int* in_sizes, int n_in,
                              void* d_out, int out_size) {
    const float* inputs = (const float*)d_in[0];
    const float* Wih0 = (const float*)d_in[1];
    const float* Whh0 = (const float*)d_in[2];
    const float* bih0 = (const float*)d_in[3];
    const float* bhh0 = (const float*)d_in[4];
    const float* Wih1 = (const float*)d_in[5];
    const float* Whh1 = (const float*)d_in[6];
    const float* bih1 = (const float*)d_in[7];
    const float* bhh1 = (const float*)d_in[8];
    const float* Wfc  = (const float*)d_in[9];
    const float* bfc  = (const float*)d_in[10];
    float* out = (float*)d_out;

    cudaFuncSetAttribute(lstm_main, cudaFuncAttributeMaxDynamicSharedMemorySize, SMEMB);

    pack0<<<(KT0B*64*32+255)/256, 256>>>(Wih0, Whh0);
    pack1<<<(KT1B*64*32+255)/256, 256>>>(Wih1, Whh1);
    packb<<<1, 512>>>(bih0, bhh0, bih1, bhh1);
    lstm_main<<<NB, NT, SMEMB>>>(inputs, Wfc, bfc, out);
}

// round 12
// speedup vs baseline: 2.1069x; 1.2945x over previous
#include <cuda_runtime.h>
#include <cuda_fp16.h>
#include <cstdint>

#define TSTEPS 60
#define LB 48
#define HZ 12
#define TILE 64
#define NB 128
#define NT 512
#define KT0B 9          // k16 tiles, layer0 (K=136 padded to 144)
#define KT1B 16         // k16 tiles, layer1 (K=256)
#define SMEMF 31104
#define SMEMB (SMEMF*4)

__device__ uint4 g_B0[KT0B*64*32];
__device__ uint4 g_B1[KT1B*64*32];
__device__ float g_bs0[512], g_bs1[512];

__device__ __forceinline__ uint32_t pk2h(float a, float b){
    __half2 t = __floats2half2_rn(a, b);    // .x = a = even k (low halfword)
    return *reinterpret_cast<uint32_t*>(&t);
}

// split v into fp16 hi + fp16 lo residual
__device__ __forceinline__ void hsplit(float v, float& hi, float& lo){
    __half h = __float2half_rn(v);
    hi = __half2float(h);
    lo = v - hi;
}

__global__ void pack0(const float* __restrict__ Wih, const float* __restrict__ Whh){
    int idx = blockIdx.x*256 + threadIdx.x;
    if (idx >= KT0B*64*32) return;
    int lane = idx&31, nt = (idx>>5)&63, kt = idx>>11;
    int np = nt*8 + (lane>>2);
    int on = (np&3)*128 + (np>>2);           // gate-interleaved col P=4j+gate
    int kb = kt*16 + (lane&3)*2;
    float v[4], h[4], l[4];
    int ks[4] = {kb, kb+1, kb+8, kb+9};
#pragma unroll
    for(int i=0;i<4;i++){
        int k = ks[i];
        v[i] = (k<8) ? Wih[on*8+k] : (k<136 ? Whh[on*128 + (k-8)] : 0.f);
        hsplit(v[i], h[i], l[i]);
    }
    g_B0[idx] = make_uint4(pk2h(h[0],h[1]), pk2h(h[2],h[3]), pk2h(l[0],l[1]), pk2h(l[2],l[3]));
}

__global__ void pack1(const float* __restrict__ Wih, const float* __restrict__ Whh){
    int idx = blockIdx.x*256 + threadIdx.x;
    if (idx >= KT1B*64*32) return;
    int lane = idx&31, nt = (idx>>5)&63, kt = idx>>11;
    int np = nt*8 + (lane>>2);
    int on = (np&3)*128 + (np>>2);
    int kb = kt*16 + (lane&3)*2;
    float v[4], h[4], l[4];
    int ks[4] = {kb, kb+1, kb+8, kb+9};
#pragma unroll
    for(int i=0;i<4;i++){
        int k = ks[i];
        v[i] = (k<128) ? Wih[on*128+k] : Whh[on*128 + (k-128)];
        hsplit(v[i], h[i], l[i]);
    }
    g_B1[idx] = make_uint4(pk2h(h[0],h[1]), pk2h(h[2],h[3]), pk2h(l[0],l[1]), pk2h(l[2],l[3]));
}

__global__ void packb(const float* a,const float* b,const float* c,const float* d){
    int P = threadIdx.x;
    int on = (P&3)*128 + (P>>2);
    g_bs0[P] = a[on]+b[on];
    g_bs1[P] = c[on]+d[on];
}

__device__ __forceinline__ void mma16(float (&c)[4], uint4 a, uint32_t b0, uint32_t b1){
    asm volatile("mma.sync.aligned.m16n8k16.row.col.f32.f16.f16.f32 "
        "{%0,%1,%2,%3},{%4,%5,%6,%7},{%8,%9},{%0,%1,%2,%3};"
        : "+f"(c[0]),"+f"(c[1]),"+f"(c[2]),"+f"(c[3])
        : "r"(a.x),"r"(a.y),"r"(a.z),"r"(a.w),"r"(b0),"r"(b1));
}

// whole-layer GEMM with rolling B prefetch.
// Each warp: M=64 (4 mt), N=32 (4 nt). 2 passes: a·bhi + a·blo.
template<int KTB>
__device__ __forceinline__ void gemm_layer(float (&acc)[4][4][4],
        const uint4* __restrict__ AH, const uint4* __restrict__ Bw, int lane){
#pragma unroll
    for(int mt=0;mt<4;mt++)
#pragma unroll
        for(int nt=0;nt<4;nt++)
#pragma unroll
            for(int i=0;i<4;i++) acc[mt][nt][i]=0.f;
    uint4 bc[4], bn[4];
#pragma unroll
    for(int i=0;i<4;i++) bc[i] = Bw[i*32+lane];
#pragma unroll 2
    for(int kt=0; kt<KTB; kt++){
        if(kt+1<KTB){
            const uint4* Bn = Bw + (size_t)(kt+1)*2048;
#pragma unroll
            for(int i=0;i<4;i++) bn[i] = Bn[i*32+lane];
        }
        uint4 a[4];
#pragma unroll
        for(int mt=0;mt<4;mt++) a[mt] = AH[(mt*KTB+kt)*32+lane];
#pragma unroll
        for(int nt=0;nt<4;nt++)
#pragma unroll
            for(int mt=0;mt<4;mt++){
                mma16(acc[mt][nt], a[mt], bc[nt].x, bc[nt].y);
                mma16(acc[mt][nt], a[mt], bc[nt].z, bc[nt].w);
            }
        if(kt+1<KTB){
#pragma unroll
            for(int i=0;i<4;i++) bc[i]=bn[i];
        }
    }
}

__device__ __forceinline__ float sigf(float x){ return __fdividef(1.f, 1.f+__expf(-x)); }
__device__ __forceinline__ float tanhfast(float x){ return __fdividef(2.f, 1.f+__expf(-2.f*x)) - 1.f; }

// store one h element (fp16) into an mma-A-fragment smem buffer
__device__ __forceinline__ void stfrag(uint32_t* FH, int KTB,
        int mt, int gp, int odd, int k, __half hb){
    int kk = k & 15, kt = k >> 4;
    int reg = odd + ((kk>>3)<<1);
    int lane_a = (gp<<2) + ((kk&7)>>1);
    int u = (((mt*KTB + kt)*32 + lane_a)<<2) + reg;
    ((__half*)FH)[u*2 + (kk&1)] = hb;
}

__device__ __forceinline__ void epilogue(float (&acc)[4][4][4], int w,int lane,int c4,int gp,int odd,
        const float* __restrict__ BS, float* __restrict__ CS,
        uint32_t* F1h, int kb1, int KTB1,
        uint32_t* F2h, int kb2, int KTB2, bool dual,
        const float* __restrict__ WF, float* __restrict__ PPT, bool doFC){
    float fc[4] = {0.f,0.f,0.f,0.f};
#pragma unroll
    for(int nt=0;nt<4;nt++){
        int P = w*32 + nt*8 + 2*c4;
        float b0 = BS[P], b1 = BS[P+1];
        int j = w*8 + nt*2 + (c4>>1);
        float wf = doFC ? WF[j] : 0.f;
#pragma unroll
        for(int mt=0;mt<4;mt++){
            float e0 = acc[mt][nt][0]+b0, e1 = acc[mt][nt][1]+b1;
            float e2 = acc[mt][nt][2]+b0, e3 = acc[mt][nt][3]+b1;
            float s0 = odd ? e0 : e2, s1 = odd ? e1 : e3;
            float r0 = __shfl_xor_sync(0xffffffffu, s0, 1);
            float r1 = __shfl_xor_sync(0xffffffffu, s1, 1);
            float gi = odd ? r0 : e0, gf = odd ? r1 : e1;
            float gg = odd ? e2 : r0, go = odd ? e3 : r1;
            int row = mt*16 + gp + 8*odd;
            float cO = CS[row*133 + j];
            float i_ = sigf(gi), f_ = sigf(gf), o_ = sigf(go);
            float g_ = tanhfast(gg);
            float cN = f_*cO + i_*g_;
            float hN = o_*tanhfast(cN);
            CS[row*133 + j] = cN;
            __half hb = __float2half_rn(hN);
            stfrag(F1h, KTB1, mt, gp, odd, kb1 + j, hb);
            if(dual) stfrag(F2h, KTB2, mt, gp, odd, kb2 + j, hb);
            fc[mt] += wf*hN;
        }
    }
    if(doFC){
#pragma unroll
        for(int mt=0;mt<4;mt++){
            float s = fc[mt] + __shfl_xor_sync(0xffffffffu, fc[mt], 2);
            if((lane&2)==0) atomicAdd(&PPT[mt*16 + gp + 8*odd], s);
        }
    }
}

__global__ void __launch_bounds__(NT,1) lstm_main(const float* __restrict__ inputs,
        const float* __restrict__ Wfc, const float* __restrict__ bfc,
        float* __restrict__ out){
    extern __shared__ float sm[];
    uint32_t* F1H = (uint32_t*)sm;            // 4*16*32*4 = 8192 u32
    uint32_t* F0H = (uint32_t*)(sm+8192);     // 4*9*32*4 = 4608
    float* CS0 = sm+12800;                    // 64*133 = 8512
    float* CS1 = sm+21312;
    float* BS0 = sm+29824;
    float* BS1 = sm+30336;
    float* WFs = sm+30848;
    float* PRD = sm+30976;
    float* PPT = sm+31040;

    int tid = threadIdx.x, w = tid>>5, lane = tid&31;
    int c4 = lane&3, gp = lane>>2, odd = c4&1;
    int rb = blockIdx.x*TILE;

    for(int i=tid;i<SMEMF;i+=NT) sm[i]=0.f;
    __syncthreads();
    for(int i=tid;i<512;i+=NT){ BS0[i]=g_bs0[i]; BS1[i]=g_bs1[i]; }
    if(tid<128) WFs[tid]=Wfc[tid];
    __syncthreads();
    float bfcv = bfc[0];

    for(int t=0;t<TSTEPS;t++){
        // scatter x_t into F0 frags, k = d (BG feedback for decode steps)
        if(tid < 512){
            int row=tid>>3, d=tid&7;
            float v = inputs[(size_t)(rb+row)*(TSTEPS*8) + t*8 + d];
            if(d==0 && t>LB) v = PRD[row];
            __half hb = __float2half_rn(v);
            int mt=row>>4, rr=row&15;
            int reg = (rr>>3);
            int lane_a = ((rr&7)<<2) + (d>>1);
            int u = ((mt*KT0B*32 + lane_a)<<2) + reg;
            ((__half*)F0H)[u*2 + (d&1)] = hb;
        }
        __syncthreads();

        float acc[4][4][4];
        // -------- layer 0: A=[x | h0_old], K=136 (9 k16 tiles) --------
        gemm_layer<KT0B>(acc, (const uint4*)F0H, g_B0 + (size_t)w*4*32, lane);
        __syncthreads();   // all reads of F0 h0_old done
        // h0_new -> F0 (k=8+j, next step) and F1 (k=j, layer1 now)
        epilogue(acc, w,lane,c4,gp,odd, BS0, CS0,
                 F0H, 8, KT0B, F1H, 0, KT1B, true,
                 WFs, PPT, false);
        __syncthreads();

        // -------- layer 1: A=[h0_new | h1_old], K=256 (16 k16 tiles) --------
        gemm_layer<KT1B>(acc, (const uint4*)F1H, g_B1 + (size_t)w*4*32, lane);
        __syncthreads();   // all reads of F1 h1_old done
        bool dec = (t>=LB);
        epilogue(acc, w,lane,c4,gp,odd, BS1, CS1,
                 F1H, 128, KT1B, (uint32_t*)0, 0, 0, false,
                 WFs, PPT, dec);
        __syncthreads();

        if(dec){
            if(tid<64){
                float p = PPT[tid] + bfcv;
                PRD[tid] = p; PPT[tid] = 0.f;
                out[(size_t)(rb+tid)*HZ + (t-LB)] = p;
            }
            __syncthreads();
        }
    }
}

extern "C" void kernel_launch(void* const* d_in, const int* in_sizes, int n_in,
                              void* d_out, int out_size) {
    const float* inputs = (const float*)d_in[0];
    const float* Wih0 = (const float*)d_in[1];
    const float* Whh0 = (const float*)d_in[2];
    const float* bih0 = (const float*)d_in[3];
    const float* bhh0 = (const float*)d_in[4];
    const float* Wih1 = (const float*)d_in[5];
    const float* Whh1 = (const float*)d_in[6];
    const float* bih1 = (const float*)d_in[7];
    const float* bhh1 = (const float*)d_in[8];
    const float* Wfc  = (const float*)d_in[9];
    const float* bfc  = (const float*)d_in[10];
    float* out = (float*)d_out;

    cudaFuncSetAttribute(lstm_main, cudaFuncAttributeMaxDynamicSharedMemorySize, SMEMB);

    pack0<<<(KT0B*64*32+255)/256, 256>>>(Wih0, Whh0);
    pack1<<<(KT1B*64*32+255)/256, 256>>>(Wih1, Whh1);
    packb<<<1, 512>>>(bih0, bhh0, bih1, bhh1);
    lstm_main<<<NB, NT, SMEMB>>>(inputs, Wfc, bfc, out);
}

// round 14
// speedup vs baseline: 3.5449x; 1.6826x over previous
#include <cuda_runtime.h>
#include <cuda_fp16.h>
#include <cstdint>

#define TSTEPS 60
#define LB 48
#define HZ 12
#define TILE 64
#define NB 128
#define NT 512
#define KT0P 10         // padded k16 tiles, layer0 (K=136 -> 160)
#define KT1P 16         // k16 tiles, layer1 (K=256)
#define G0 5            // k32 groups layer0
#define G1 8            // k32 groups layer1
#define SMEMF 31616
#define SMEMB (SMEMF*4)

__device__ uint4 g_B0[G0*64*32];
__device__ uint4 g_B1[G1*64*32];
__device__ float g_bs0[512], g_bs1[512];

__device__ __forceinline__ uint32_t pk2h(float a, float b){
    __half2 t = __floats2half2_rn(a, b);    // .x = a = even k (low halfword)
    return *reinterpret_cast<uint32_t*>(&t);
}

__global__ void pack0(const float* __restrict__ Wih, const float* __restrict__ Whh){
    int idx = blockIdx.x*256 + threadIdx.x;
    if (idx >= G0*64*32) return;
    int lane = idx&31, ntg = (idx>>5)&63, g = idx>>11;
    int np = ntg*8 + (lane>>2);
    int on = (np&3)*128 + (np>>2);           // gate-interleaved col P=4j+gate
    uint32_t r[4];
#pragma unroll
    for(int t=0;t<2;t++){
        int kb = (2*g+t)*16 + (lane&3)*2;
        float v[4];
        int ks[4] = {kb, kb+1, kb+8, kb+9};
#pragma unroll
        for(int i=0;i<4;i++){
            int k = ks[i];
            v[i] = (k<8) ? Wih[on*8+k] : (k<136 ? Whh[on*128 + (k-8)] : 0.f);
        }
        r[2*t]   = pk2h(v[0], v[1]);
        r[2*t+1] = pk2h(v[2], v[3]);
    }
    g_B0[idx] = make_uint4(r[0], r[1], r[2], r[3]);
}

__global__ void pack1(const float* __restrict__ Wih, const float* __restrict__ Whh){
    int idx = blockIdx.x*256 + threadIdx.x;
    if (idx >= G1*64*32) return;
    int lane = idx&31, ntg = (idx>>5)&63, g = idx>>11;
    int np = ntg*8 + (lane>>2);
    int on = (np&3)*128 + (np>>2);
    uint32_t r[4];
#pragma unroll
    for(int t=0;t<2;t++){
        int kb = (2*g+t)*16 + (lane&3)*2;
        float v[4];
        int ks[4] = {kb, kb+1, kb+8, kb+9};
#pragma unroll
        for(int i=0;i<4;i++){
            int k = ks[i];
            v[i] = (k<128) ? Wih[on*128+k] : Whh[on*128 + (k-128)];
        }
        r[2*t]   = pk2h(v[0], v[1]);
        r[2*t+1] = pk2h(v[2], v[3]);
    }
    g_B1[idx] = make_uint4(r[0], r[1], r[2], r[3]);
}

__global__ void packb(const float* a,const float* b,const float* c,const float* d){
    int P = threadIdx.x;
    int on = (P&3)*128 + (P>>2);
    g_bs0[P] = a[on]+b[on];
    g_bs1[P] = c[on]+d[on];
}

__device__ __forceinline__ void mma16(float (&c)[4], uint4 a, uint32_t b0, uint32_t b1){
    asm volatile("mma.sync.aligned.m16n8k16.row.col.f32.f16.f16.f32 "
        "{%0,%1,%2,%3},{%4,%5,%6,%7},{%8,%9},{%0,%1,%2,%3};"
        : "+f"(c[0]),"+f"(c[1]),"+f"(c[2]),"+f"(c[3])
        : "r"(a.x),"r"(a.y),"r"(a.z),"r"(a.w),"r"(b0),"r"(b1));
}

// whole-layer GEMM over k32 groups with rolling B prefetch.
// Each warp: M=64 (4 mt), N=32 (4 nt), single fp16 pass.
// B uint4 = (kt=2g frag .x.y, kt=2g+1 frag .x.y)
template<int G, int KTP>
__device__ __forceinline__ void gemm_layer(float (&acc)[4][4][4],
        const uint4* __restrict__ AH, const uint4* __restrict__ Bw, int lane){
#pragma unroll
    for(int mt=0;mt<4;mt++)
#pragma unroll
        for(int nt=0;nt<4;nt++)
#pragma unroll
            for(int i=0;i<4;i++) acc[mt][nt][i]=0.f;
    uint4 bc[4], bn[4];
#pragma unroll
    for(int i=0;i<4;i++) bc[i] = Bw[i*32+lane];
#pragma unroll
    for(int g=0; g<G; g++){
        if(g+1<G){
            const uint4* Bn = Bw + (size_t)(g+1)*2048;
#pragma unroll
            for(int i=0;i<4;i++) bn[i] = Bn[i*32+lane];
        }
        uint4 a0[4], a1[4];
#pragma unroll
        for(int mt=0;mt<4;mt++){
            a0[mt] = AH[(mt*KTP + 2*g  )*32+lane];
            a1[mt] = AH[(mt*KTP + 2*g+1)*32+lane];
        }
#pragma unroll
        for(int nt=0;nt<4;nt++)
#pragma unroll
            for(int mt=0;mt<4;mt++){
                mma16(acc[mt][nt], a0[mt], bc[nt].x, bc[nt].y);
                mma16(acc[mt][nt], a1[mt], bc[nt].z, bc[nt].w);
            }
        if(g+1<G){
#pragma unroll
            for(int i=0;i<4;i++) bc[i]=bn[i];
        }
    }
}

__device__ __forceinline__ float sigf(float x){ return __fdividef(1.f, 1.f+__expf(-x)); }
__device__ __forceinline__ float tanhfast(float x){ return __fdividef(2.f, 1.f+__expf(-2.f*x)) - 1.f; }

// store one h element (fp16) into an mma-A-fragment smem buffer
__device__ __forceinline__ void stfrag(uint32_t* FH, int KTP,
        int mt, int gp, int odd, int k, __half hb){
    int kk = k & 15, kt = k >> 4;
    int reg = odd + ((kk>>3)<<1);
    int lane_a = (gp<<2) + ((kk&7)>>1);
    int u = (((mt*KTP + kt)*32 + lane_a)<<2) + reg;
    ((__half*)FH)[u*2 + (kk&1)] = hb;
}

__device__ __forceinline__ void epilogue(float (&acc)[4][4][4], int w,int lane,int c4,int gp,int odd,
        const float* __restrict__ BS, float* __restrict__ CS,
        uint32_t* F1h, int kb1, int KTP1,
        uint32_t* F2h, int kb2, int KTP2, bool dual,
        const float* __restrict__ WF, float* __restrict__ PPT, bool doFC){
    float fc[4] = {0.f,0.f,0.f,0.f};
#pragma unroll
    for(int nt=0;nt<4;nt++){
        int P = w*32 + nt*8 + 2*c4;
        float b0 = BS[P], b1 = BS[P+1];
        int j = w*8 + nt*2 + (c4>>1);
        float wf = doFC ? WF[j] : 0.f;
#pragma unroll
        for(int mt=0;mt<4;mt++){
            float e0 = acc[mt][nt][0]+b0, e1 = acc[mt][nt][1]+b1;
            float e2 = acc[mt][nt][2]+b0, e3 = acc[mt][nt][3]+b1;
            float s0 = odd ? e0 : e2, s1 = odd ? e1 : e3;
            float r0 = __shfl_xor_sync(0xffffffffu, s0, 1);
            float r1 = __shfl_xor_sync(0xffffffffu, s1, 1);
            float gi = odd ? r0 : e0, gf = odd ? r1 : e1;
            float gg = odd ? e2 : r0, go = odd ? e3 : r1;
            int row = mt*16 + gp + 8*odd;
            float cO = CS[row*133 + j];
            float i_ = sigf(gi), f_ = sigf(gf), o_ = sigf(go);
            float g_ = tanhfast(gg);
            float cN = f_*cO + i_*g_;
            float hN = o_*tanhfast(cN);
            CS[row*133 + j] = cN;
            __half hb = __float2half_rn(hN);
            stfrag(F1h, KTP1, mt, gp, odd, kb1 + j, hb);
            if(dual) stfrag(F2h, KTP2, mt, gp, odd, kb2 + j, hb);
            fc[mt] += wf*hN;
        }
    }
    if(doFC){
#pragma unroll
        for(int mt=0;mt<4;mt++){
            float s = fc[mt] + __shfl_xor_sync(0xffffffffu, fc[mt], 2);
            if((lane&2)==0) atomicAdd(&PPT[mt*16 + gp + 8*odd], s);
        }
    }
}

__global__ void __launch_bounds__(NT,1) lstm_main(const float* __restrict__ inputs,
        const float* __restrict__ Wfc, const float* __restrict__ bfc,
        float* __restrict__ out){
    extern __shared__ float sm[];
    uint32_t* F1H = (uint32_t*)sm;            // 4*16*32*4 = 8192 u32
    uint32_t* F0H = (uint32_t*)(sm+8192);     // 4*10*32*4 = 5120 u32
    float* CS0 = sm+13312;                    // 64*133 = 8512
    float* CS1 = sm+21824;
    float* BS0 = sm+30336;
    float* BS1 = sm+30848;
    float* WFs = sm+31360;
    float* PRD = sm+31488;
    float* PPT = sm+31552;

    int tid = threadIdx.x, w = tid>>5, lane = tid&31;
    int c4 = lane&3, gp = lane>>2, odd = c4&1;
    int rb = blockIdx.x*TILE;

    for(int i=tid;i<SMEMF;i+=NT) sm[i]=0.f;
    __syncthreads();
    if(tid<512){ BS0[tid]=g_bs0[tid]; BS1[tid]=g_bs1[tid]; }
    if(tid<128) WFs[tid]=Wfc[tid];
    __syncthreads();
    float bfcv = bfc[0];

    for(int t=0;t<TSTEPS;t++){
        // scatter x_t into F0 frags, k = d (BG feedback for decode steps)
        if(tid < 512){
            int row=tid>>3, d=tid&7;
            float v = inputs[(size_t)(rb+row)*(TSTEPS*8) + t*8 + d];
            if(d==0 && t>LB) v = PRD[row];
            __half hb = __float2half_rn(v);
            int mt=row>>4, rr=row&15;
            int reg = (rr>>3);
            int lane_a = ((rr&7)<<2) + (d>>1);
            int u = ((mt*KT0P*32 + lane_a)<<2) + reg;
            ((__half*)F0H)[u*2 + (d&1)] = hb;
        }
        __syncthreads();

        float acc[4][4][4];
        // -------- layer 0: A=[x | h0_old], K=136 (5 k32 groups, padded) --------
        gemm_layer<G0, KT0P>(acc, (const uint4*)F0H, g_B0 + (size_t)w*4*32, lane);
        __syncthreads();   // all reads of F0 h0_old done
        // h0_new -> F0 (k=8+j, next step) and F1 (k=j, layer1 now)
        epilogue(acc, w,lane,c4,gp,odd, BS0, CS0,
                 F0H, 8, KT0P, F1H, 0, KT1P, true,
                 WFs, PPT, false);
        __syncthreads();

        // -------- layer 1: A=[h0_new | h1_old], K=256 (8 k32 groups) --------
        gemm_layer<G1, KT1P>(acc, (const uint4*)F1H, g_B1 + (size_t)w*4*32, lane);
        __syncthreads();   // all reads of F1 h1_old done
        bool dec = (t>=LB);
        epilogue(acc, w,lane,c4,gp,odd, BS1, CS1,
                 F1H, 128, KT1P, (uint32_t*)0, 0, 0, false,
                 WFs, PPT, dec);
        __syncthreads();

        if(dec){
            if(tid<64){
                float p = PPT[tid] + bfcv;
                PRD[tid] = p; PPT[tid] = 0.f;
                out[(size_t)(rb+tid)*HZ + (t-LB)] = p;
            }
            __syncthreads();
        }
    }
}

extern "C" void kernel_launch(void* const* d_in, const int* in_sizes, int n_in,
                              void* d_out, int out_size) {
    const float* inputs = (const float*)d_in[0];
    const float* Wih0 = (const float*)d_in[1];
    const float* Whh0 = (const float*)d_in[2];
    const float* bih0 = (const float*)d_in[3];
    const float* bhh0 = (const float*)d_in[4];
    const float* Wih1 = (const float*)d_in[5];
    const float* Whh1 = (const float*)d_in[6];
    const float* bih1 = (const float*)d_in[7];
    const float* bhh1 = (const float*)d_in[8];
    const float* Wfc  = (const float*)d_in[9];
    const float* bfc  = (const float*)d_in[10];
    float* out = (float*)d_out;

    cudaFuncSetAttribute(lstm_main, cudaFuncAttributeMaxDynamicSharedMemorySize, SMEMB);

    pack0<<<(G0*64*32+255)/256, 256>>>(Wih0, Whh0);
    pack1<<<(G1*64*32+255)/256, 256>>>(Wih1, Whh1);
    packb<<<1, 512>>>(bih0, bhh0, bih1, bhh1);
    lstm_main<<<NB, NT, SMEMB>>>(inputs, Wfc, bfc, out);
}

// round 15
// speedup vs baseline: 3.9343x; 1.1098x over previous
#include <cuda_runtime.h>
#include <cuda_fp16.h>
#include <cstdint>

#define TSTEPS 60
#define LB 48
#define HZ 12
#define TILE 64
#define NB 128
#define NT 512
#define KT0P 10         // padded k16 tiles, layer0 (K=136 -> 160)
#define KT1P 16         // k16 tiles, layer1 (K=256)
#define G0 5            // k32 groups layer0
#define G1 8            // k32 groups layer1
#define SMEMF 31616
#define SMEMB (SMEMF*4)

__device__ uint4 g_B0[G0*64*32];
__device__ uint4 g_B1[G1*64*32];
__device__ float g_bs0[512], g_bs1[512];

__device__ __forceinline__ uint32_t pk2h(float a, float b){
    __half2 t = __floats2half2_rn(a, b);    // .x = a = even k (low halfword)
    return *reinterpret_cast<uint32_t*>(&t);
}

__global__ void pack0(const float* __restrict__ Wih, const float* __restrict__ Whh){
    int idx = blockIdx.x*256 + threadIdx.x;
    if (idx >= G0*64*32) return;
    int lane = idx&31, ntg = (idx>>5)&63, g = idx>>11;
    int np = ntg*8 + (lane>>2);
    int on = (np&3)*128 + (np>>2);           // gate-interleaved col P=4j+gate
    uint32_t r[4];
#pragma unroll
    for(int t=0;t<2;t++){
        int kb = (2*g+t)*16 + (lane&3)*2;
        float v[4];
        int ks[4] = {kb, kb+1, kb+8, kb+9};
#pragma unroll
        for(int i=0;i<4;i++){
            int k = ks[i];
            v[i] = (k<8) ? Wih[on*8+k] : (k<136 ? Whh[on*128 + (k-8)] : 0.f);
        }
        r[2*t]   = pk2h(v[0], v[1]);
        r[2*t+1] = pk2h(v[2], v[3]);
    }
    g_B0[idx] = make_uint4(r[0], r[1], r[2], r[3]);
}

__global__ void pack1(const float* __restrict__ Wih, const float* __restrict__ Whh){
    int idx = blockIdx.x*256 + threadIdx.x;
    if (idx >= G1*64*32) return;
    int lane = idx&31, ntg = (idx>>5)&63, g = idx>>11;
    int np = ntg*8 + (lane>>2);
    int on = (np&3)*128 + (np>>2);
    uint32_t r[4];
#pragma unroll
    for(int t=0;t<2;t++){
        int kb = (2*g+t)*16 + (lane&3)*2;
        float v[4];
        int ks[4] = {kb, kb+1, kb+8, kb+9};
#pragma unroll
        for(int i=0;i<4;i++){
            int k = ks[i];
            v[i] = (k<128) ? Wih[on*128+k] : Whh[on*128 + (k-128)];
        }
        r[2*t]   = pk2h(v[0], v[1]);
        r[2*t+1] = pk2h(v[2], v[3]);
    }
    g_B1[idx] = make_uint4(r[0], r[1], r[2], r[3]);
}

__global__ void packb(const float* a,const float* b,const float* c,const float* d){
    int P = threadIdx.x;
    int on = (P&3)*128 + (P>>2);
    g_bs0[P] = a[on]+b[on];
    g_bs1[P] = c[on]+d[on];
}

__device__ __forceinline__ void mma16(float (&c)[4], uint4 a, uint32_t b0, uint32_t b1){
    asm volatile("mma.sync.aligned.m16n8k16.row.col.f32.f16.f16.f32 "
        "{%0,%1,%2,%3},{%4,%5,%6,%7},{%8,%9},{%0,%1,%2,%3};"
        : "+f"(c[0]),"+f"(c[1]),"+f"(c[2]),"+f"(c[3])
        : "r"(a.x),"r"(a.y),"r"(a.z),"r"(a.w),"r"(b0),"r"(b1));
}

// whole-layer GEMM over k32 groups with rolling B prefetch.
// Each warp: M=64 (4 mt), N=32 (4 nt), single fp16 pass.
template<int G, int KTP>
__device__ __forceinline__ void gemm_layer(float (&acc)[4][4][4],
        const uint4* __restrict__ AH, const uint4* __restrict__ Bw, int lane){
#pragma unroll
    for(int mt=0;mt<4;mt++)
#pragma unroll
        for(int nt=0;nt<4;nt++)
#pragma unroll
            for(int i=0;i<4;i++) acc[mt][nt][i]=0.f;
    uint4 bc[4], bn[4];
#pragma unroll
    for(int i=0;i<4;i++) bc[i] = Bw[i*32+lane];
#pragma unroll
    for(int g=0; g<G; g++){
        if(g+1<G){
            const uint4* Bn = Bw + (size_t)(g+1)*2048;
#pragma unroll
            for(int i=0;i<4;i++) bn[i] = Bn[i*32+lane];
        }
        uint4 a0[4], a1[4];
#pragma unroll
        for(int mt=0;mt<4;mt++){
            a0[mt] = AH[(mt*KTP + 2*g  )*32+lane];
            a1[mt] = AH[(mt*KTP + 2*g+1)*32+lane];
        }
#pragma unroll
        for(int nt=0;nt<4;nt++)
#pragma unroll
            for(int mt=0;mt<4;mt++){
                mma16(acc[mt][nt], a0[mt], bc[nt].x, bc[nt].y);
                mma16(acc[mt][nt], a1[mt], bc[nt].z, bc[nt].w);
            }
        if(g+1<G){
#pragma unroll
            for(int i=0;i<4;i++) bc[i]=bn[i];
        }
    }
}

// hardware tanh (MUFU.TANH, 1 MUFU op)
__device__ __forceinline__ float tanha(float x){
    float y; asm("tanh.approx.f32 %0, %1;" : "=f"(y) : "f"(x)); return y;
}
// sigmoid(x) = 0.5*tanh(x/2) + 0.5  (1 MUFU + FMA)
__device__ __forceinline__ float sigf(float x){
    return fmaf(tanha(0.5f*x), 0.5f, 0.5f);
}

// store one h element (fp16) into an mma-A-fragment smem buffer
__device__ __forceinline__ void stfrag(uint32_t* FH, int KTP,
        int mt, int gp, int odd, int k, __half hb){
    int kk = k & 15, kt = k >> 4;
    int reg = odd + ((kk>>3)<<1);
    int lane_a = (gp<<2) + ((kk&7)>>1);
    int u = (((mt*KTP + kt)*32 + lane_a)<<2) + reg;
    ((__half*)FH)[u*2 + (kk&1)] = hb;
}

__device__ __forceinline__ void epilogue(float (&acc)[4][4][4], int w,int lane,int c4,int gp,int odd,
        const float* __restrict__ BS, float* __restrict__ CS,
        uint32_t* F1h, int kb1, int KTP1,
        uint32_t* F2h, int kb2, int KTP2, bool dual,
        const float* __restrict__ WF, float* __restrict__ PPT, bool doFC){
    float fc[4] = {0.f,0.f,0.f,0.f};
#pragma unroll
    for(int nt=0;nt<4;nt++){
        int P = w*32 + nt*8 + 2*c4;
        float b0 = BS[P], b1 = BS[P+1];
        int j = w*8 + nt*2 + (c4>>1);
        float wf = doFC ? WF[j] : 0.f;
#pragma unroll
        for(int mt=0;mt<4;mt++){
            float e0 = acc[mt][nt][0]+b0, e1 = acc[mt][nt][1]+b1;
            float e2 = acc[mt][nt][2]+b0, e3 = acc[mt][nt][3]+b1;
            float s0 = odd ? e0 : e2, s1 = odd ? e1 : e3;
            float r0 = __shfl_xor_sync(0xffffffffu, s0, 1);
            float r1 = __shfl_xor_sync(0xffffffffu, s1, 1);
            float gi = odd ? r0 : e0, gf = odd ? r1 : e1;
            float gg = odd ? e2 : r0, go = odd ? e3 : r1;
            int row = mt*16 + gp + 8*odd;
            float cO = CS[row*133 + j];
            float i_ = sigf(gi), f_ = sigf(gf), o_ = sigf(go);
            float g_ = tanha(gg);
            float cN = f_*cO + i_*g_;
            float hN = o_*tanha(cN);
            CS[row*133 + j] = cN;
            __half hb = __float2half_rn(hN);
            stfrag(F1h, KTP1, mt, gp, odd, kb1 + j, hb);
            if(dual) stfrag(F2h, KTP2, mt, gp, odd, kb2 + j, hb);
            fc[mt] += wf*hN;
        }
    }
    if(doFC){
#pragma unroll
        for(int mt=0;mt<4;mt++){
            float s = fc[mt] + __shfl_xor_sync(0xffffffffu, fc[mt], 2);
            if((lane&2)==0) atomicAdd(&PPT[mt*16 + gp + 8*odd], s);
        }
    }
}

__global__ void __launch_bounds__(NT,1) lstm_main(const float* __restrict__ inputs,
        const float* __restrict__ Wfc, const float* __restrict__ bfc,
        float* __restrict__ out){
    extern __shared__ float sm[];
    uint32_t* F1H = (uint32_t*)sm;            // 4*16*32*4 = 8192 u32
    uint32_t* F0H = (uint32_t*)(sm+8192);     // 4*10*32*4 = 5120 u32
    float* CS0 = sm+13312;                    // 64*133 = 8512
    float* CS1 = sm+21824;
    float* BS0 = sm+30336;
    float* BS1 = sm+30848;
    float* WFs = sm+31360;
    float* PRD = sm+31488;
    float* PPT = sm+31552;

    int tid = threadIdx.x, w = tid>>5, lane = tid&31;
    int c4 = lane&3, gp = lane>>2, odd = c4&1;
    int rb = blockIdx.x*TILE;

    for(int i=tid;i<SMEMF;i+=NT) sm[i]=0.f;
    __syncthreads();
    if(tid<512){ BS0[tid]=g_bs0[tid]; BS1[tid]=g_bs1[tid]; }
    if(tid<128) WFs[tid]=Wfc[tid];
    __syncthreads();
    float bfcv = bfc[0];

    for(int t=0;t<TSTEPS;t++){
        // scatter x_t into F0 frags, k = d (BG feedback for decode steps)
        if(tid < 512){
            int row=tid>>3, d=tid&7;
            float v = inputs[(size_t)(rb+row)*(TSTEPS*8) + t*8 + d];
            if(d==0 && t>LB) v = PRD[row];
            __half hb = __float2half_rn(v);
            int mt=row>>4, rr=row&15;
            int reg = (rr>>3);
            int lane_a = ((rr&7)<<2) + (d>>1);
            int u = ((mt*KT0P*32 + lane_a)<<2) + reg;
            ((__half*)F0H)[u*2 + (d&1)] = hb;
        }
        __syncthreads();

        float acc[4][4][4];
        // -------- layer 0: A=[x | h0_old], K=136 (5 k32 groups, padded) --------
        gemm_layer<G0, KT0P>(acc, (const uint4*)F0H, g_B0 + (size_t)w*4*32, lane);
        __syncthreads();   // all reads of F0 h0_old done
        // h0_new -> F0 (k=8+j, next step) and F1 (k=j, layer1 now)
        epilogue(acc, w,lane,c4,gp,odd, BS0, CS0,
                 F0H, 8, KT0P, F1H, 0, KT1P, true,
                 WFs, PPT, false);
        __syncthreads();

        // -------- layer 1: A=[h0_new | h1_old], K=256 (8 k32 groups) --------
        gemm_layer<G1, KT1P>(acc, (const uint4*)F1H, g_B1 + (size_t)w*4*32, lane);
        __syncthreads();   // all reads of F1 h1_old done
        bool dec = (t>=LB);
        epilogue(acc, w,lane,c4,gp,odd, BS1, CS1,
                 F1H, 128, KT1P, (uint32_t*)0, 0, 0, false,
                 WFs, PPT, dec);
        __syncthreads();

        if(dec){
            if(tid<64){
                float p = PPT[tid] + bfcv;
                PRD[tid] = p; PPT[tid] = 0.f;
                out[(size_t)(rb+tid)*HZ + (t-LB)] = p;
            }
            __syncthreads();
        }
    }
}

extern "C" void kernel_launch(void* const* d_in, const int* in_sizes, int n_in,
                              void* d_out, int out_size) {
    const float* inputs = (const float*)d_in[0];
    const float* Wih0 = (const float*)d_in[1];
    const float* Whh0 = (const float*)d_in[2];
    const float* bih0 = (const float*)d_in[3];
    const float* bhh0 = (const float*)d_in[4];
    const float* Wih1 = (const float*)d_in[5];
    const float* Whh1 = (const float*)d_in[6];
    const float* bih1 = (const float*)d_in[7];
    const float* bhh1 = (const float*)d_in[8];
    const float* Wfc  = (const float*)d_in[9];
    const float* bfc  = (const float*)d_in[10];
    float* out = (float*)d_out;

    cudaFuncSetAttribute(lstm_main, cudaFuncAttributeMaxDynamicSharedMemorySize, SMEMB);

    pack0<<<(G0*64*32+255)/256, 256>>>(Wih0, Whh0);
    pack1<<<(G1*64*32+255)/256, 256>>>(Wih1, Whh1);
    packb<<<1, 512>>>(bih0, bhh0, bih1, bhh1);
    lstm_main<<<NB, NT, SMEMB>>>(inputs, Wfc, bfc, out);
}